// round 4
// baseline (speedup 1.0000x reference)
#include <cuda_runtime.h>
#include <cstdint>

#define T_STEPS 2048
#define HID 64
#define EPB 7            // batch elements per block -> 147 blocks = single wave
#define NTHR 512

typedef unsigned long long u64;

// ---------- f32x2 packed math ----------
__device__ __forceinline__ u64 fma2(u64 a, u64 b, u64 c) {
    u64 d; asm("fma.rn.f32x2 %0, %1, %2, %3;" : "=l"(d) : "l"(a), "l"(b), "l"(c)); return d;
}
__device__ __forceinline__ u64 add2(u64 a, u64 b) {
    u64 d; asm("add.rn.f32x2 %0, %1, %2;" : "=l"(d) : "l"(a), "l"(b)); return d;
}
__device__ __forceinline__ u64 pack2(float lo, float hi) {
    u64 d; asm("mov.b64 %0, {%1, %2};" : "=l"(d) : "f"(lo), "f"(hi)); return d;
}
__device__ __forceinline__ float2 unpack2(u64 v) {
    float a, b; asm("mov.b64 {%0, %1}, %2;" : "=f"(a), "=f"(b) : "l"(v));
    return make_float2(a, b);
}

// ---------- activations (EX2/RCP exact-ish; rel err ~1e-6) ----------
__device__ __forceinline__ float sigmoid_(float x) {
    return __fdividef(1.0f, 1.0f + __expf(-x));
}
__device__ __forceinline__ float tanh_(float x) {
    float e = __expf(2.0f * fabsf(x));
    float t = 1.0f - __fdividef(2.0f, e + 1.0f);
    return copysignf(t, x);
}

extern __shared__ char smem_raw[];

// SMEM layout (bytes)
#define OFF_X     0
#define SZ_X      (EPB * T_STEPS * 4)                    // 57344
#define OFF_H1    (OFF_X + SZ_X)
#define SZ_H      (2 * EPB * HID * 4)                    // 3584
#define OFF_H2    (OFF_H1 + SZ_H)
#define OFF_PSH0  (OFF_H2 + SZ_H)
#define SZ_PSH    (4 * EPB * 128 * 8)                    // 28672 (float2)
#define OFF_PSH1  (OFF_PSH0 + SZ_PSH)
#define OFF_B0    (OFF_PSH1 + SZ_PSH)
#define OFF_B1    (OFF_B0 + HID * 16)
#define OFF_XW    (OFF_B1 + HID * 16)
#define SMEM_TOTAL (OFF_XW + HID * 16)                   // ~125 KB

// =====================================================================================
// Fused 2-layer LSTM + FC, persistent, one wave. 512 threads:
//   u  = tid & 63    : hidden unit
//   gp = (tid>>6)&1  : gate-pair (0:i,f  1:g,o)
//   s  = tid >> 7    : 4-way k-split
// Pipeline: iteration j phase1 = layer0 partials(t=j) + layer1 partials(t=j-1);
//           phase2 activates both. 2 barriers per step for BOTH layers.
// =====================================================================================
__global__ void __launch_bounds__(NTHR, 1)
lstm_fused(const float* __restrict__ x,
           const float* __restrict__ Wih0, const float* __restrict__ Whh0,
           const float* __restrict__ bih0, const float* __restrict__ bhh0,
           const float* __restrict__ Wih1, const float* __restrict__ Whh1,
           const float* __restrict__ bih1, const float* __restrict__ bhh1,
           const float* __restrict__ fcW,  const float* __restrict__ fcb,
           float* __restrict__ out, int B)
{
    float*  x_sh  = (float*)(smem_raw + OFF_X);     // [EPB][T_STEPS]
    float*  h1_sh = (float*)(smem_raw + OFF_H1);    // [2][EPB][HID]
    float*  h2_sh = (float*)(smem_raw + OFF_H2);    // [2][EPB][HID]
    float2* psh0  = (float2*)(smem_raw + OFF_PSH0); // [4][EPB][128]
    float2* psh1  = (float2*)(smem_raw + OFF_PSH1); // [4][EPB][128]
    float4* b0_sh = (float4*)(smem_raw + OFF_B0);   // [HID] gate biases layer0
    float4* b1_sh = (float4*)(smem_raw + OFF_B1);   // [HID] gate biases layer1
    float4* xw_sh = (float4*)(smem_raw + OFF_XW);   // [HID] Wih0 per gate

    const int tid = threadIdx.x;
    const int u  = tid & 63;
    const int gp = (tid >> 6) & 1;
    const int s  = tid >> 7;
    const int q  = s * 2 + gp;          // phase-2 slot 0..7
    const int b0 = blockIdx.x * EPB;

    // ---- stage x rows (coalesced) ----
    for (int i = tid; i < EPB * T_STEPS / 4; i += NTHR) {
        int e = i / (T_STEPS / 4), c = i % (T_STEPS / 4);
        int be = b0 + e; if (be > B - 1) be = B - 1;
        ((float4*)x_sh)[i] = ((const float4*)(x + (size_t)be * T_STEPS))[c];
    }
    // ---- biases / xw to SMEM ----
    if (tid < HID) {
        b0_sh[tid] = make_float4(bih0[tid]       + bhh0[tid],
                                 bih0[64 + tid]  + bhh0[64 + tid],
                                 bih0[128 + tid] + bhh0[128 + tid],
                                 bih0[192 + tid] + bhh0[192 + tid]);
        b1_sh[tid] = make_float4(bih1[tid]       + bhh1[tid],
                                 bih1[64 + tid]  + bhh1[64 + tid],
                                 bih1[128 + tid] + bhh1[128 + tid],
                                 bih1[192 + tid] + bhh1[192 + tid]);
        xw_sh[tid] = make_float4(Wih0[tid], Wih0[64 + tid],
                                 Wih0[128 + tid], Wih0[192 + tid]);
    }
    // ---- zero h states ----
    for (int i = tid; i < 2 * EPB * HID; i += NTHR) { h1_sh[i] = 0.0f; h2_sh[i] = 0.0f; }

    // ---- register weights ----
    // layer0: gates (2gp, 2gp+1), k in [16s,16s+16), k-pair packed
    const int rA = (gp * 2) * 64 + u, rB = (gp * 2 + 1) * 64 + u;
    u64 w0A[8], w0B[8];
    {
        const int k0 = s * 16;
#pragma unroll
        for (int p = 0; p < 8; ++p) {
            w0A[p] = pack2(Whh0[rA * 64 + k0 + 2 * p], Whh0[rA * 64 + k0 + 2 * p + 1]);
            w0B[p] = pack2(Whh0[rB * 64 + k0 + 2 * p], Whh0[rB * 64 + k0 + 2 * p + 1]);
        }
    }
    // layer1: k in [32s,32s+32): s<2 -> Wih1 (input h1), s>=2 -> Whh1 (recurrent h2)
    u64 w1A[16], w1B[16];
    {
        const float* Wsrc = (s < 2) ? Wih1 : Whh1;
        const int kb = (s & 1) * 32;
#pragma unroll
        for (int p = 0; p < 16; ++p) {
            w1A[p] = pack2(Wsrc[rA * 64 + kb + 2 * p], Wsrc[rA * 64 + kb + 2 * p + 1]);
            w1B[p] = pack2(Wsrc[rB * 64 + kb + 2 * p], Wsrc[rB * 64 + kb + 2 * p + 1]);
        }
    }

    float cA = 0.0f, cB = 0.0f;   // c-states for phase-2 tasks q and q+8
    __syncthreads();

#pragma unroll 1
    for (int j = 0; j <= T_STEPS; ++j) {
        const int rb = j & 1;          // read slot: h1[j-1], h2[j-2]
        const int wb = rb ^ 1;         // write slot: h1[j], h2[j-1]

        // ================= phase 1 =================
        if (j < T_STEPS) {             // layer0 partials for t=j
#pragma unroll 1
            for (int e = 0; e < EPB; ++e) {
                const ulonglong2* hp =
                    (const ulonglong2*)&h1_sh[(rb * EPB + e) * HID + s * 16];
                u64 aA = 0, aB = 0;
#pragma unroll
                for (int p = 0; p < 4; ++p) {
                    ulonglong2 v = hp[p];
                    aA = fma2(v.x, w0A[2 * p], aA);     aB = fma2(v.x, w0B[2 * p], aB);
                    aA = fma2(v.y, w0A[2 * p + 1], aA); aB = fma2(v.y, w0B[2 * p + 1], aB);
                }
                float2 fa = unpack2(aA), fb = unpack2(aB);
                psh0[(s * EPB + e) * 128 + gp * 64 + u] =
                    make_float2(fa.x + fa.y, fb.x + fb.y);
            }
        }
        if (j > 0) {                   // layer1 partials for t=j-1
#pragma unroll 1
            for (int e = 0; e < EPB; ++e) {
                const ulonglong2* hp = (s < 2)
                    ? (const ulonglong2*)&h1_sh[(rb * EPB + e) * HID + s * 32]
                    : (const ulonglong2*)&h2_sh[(rb * EPB + e) * HID + (s - 2) * 32];
                u64 aA = 0, aB = 0;
#pragma unroll
                for (int p = 0; p < 8; ++p) {
                    ulonglong2 v = hp[p];
                    aA = fma2(v.x, w1A[2 * p], aA);     aB = fma2(v.x, w1B[2 * p], aB);
                    aA = fma2(v.y, w1A[2 * p + 1], aA); aB = fma2(v.y, w1B[2 * p + 1], aB);
                }
                float2 fa = unpack2(aA), fb = unpack2(aB);
                psh1[(s * EPB + e) * 128 + gp * 64 + u] =
                    make_float2(fa.x + fa.y, fb.x + fb.y);
            }
        }
        __syncthreads();

        // ================= phase 2 =================
        // task r: r<7 -> (layer0, e=r) valid if j<T; r>=7 -> (layer1, e=r-7) valid if j>0
#pragma unroll
        for (int pass = 0; pass < 2; ++pass) {
            const int r = q + pass * 8;
            if (r >= 14) break;
            const int L = (r < 7) ? 0 : 1;
            const int e = (r < 7) ? r : r - 7;
            const bool valid = L ? (j > 0) : (j < T_STEPS);
            if (valid) {
                const u64* base = (const u64*)(L ? psh1 : psh0);
                u64 sif = base[(0 * EPB + e) * 128 + u];
                u64 sgo = base[(0 * EPB + e) * 128 + 64 + u];
#pragma unroll
                for (int sp = 1; sp < 4; ++sp) {
                    sif = add2(sif, base[(sp * EPB + e) * 128 + u]);
                    sgo = add2(sgo, base[(sp * EPB + e) * 128 + 64 + u]);
                }
                float2 v_if = unpack2(sif), v_go = unpack2(sgo);
                float4 bias = (L ? b1_sh : b0_sh)[u];
                float pi = v_if.x + bias.x, pf = v_if.y + bias.y;
                float pg = v_go.x + bias.z, po = v_go.y + bias.w;
                if (L == 0) {
                    float xv = x_sh[e * T_STEPS + j];
                    float4 xw = xw_sh[u];
                    pi += xv * xw.x; pf += xv * xw.y;
                    pg += xv * xw.z; po += xv * xw.w;
                }
                float gi = sigmoid_(pi), gf = sigmoid_(pf);
                float gg = tanh_(pg),    go = sigmoid_(po);
                float& cs = pass ? cB : cA;
                cs = gf * cs + gi * gg;
                float h = go * tanh_(cs);
                (L ? h2_sh : h1_sh)[(wb * EPB + e) * HID + u] = h;
            }
        }
        __syncthreads();
    }

    // ---- final FC: h2[T-1] sits in h2_sh slot 1 (wb of last iteration) ----
    if (tid < EPB * 32) {
        const int e = tid >> 5, lane = tid & 31;
        float acc = h2_sh[(1 * EPB + e) * HID + lane] * fcW[lane]
                  + h2_sh[(1 * EPB + e) * HID + 32 + lane] * fcW[32 + lane];
#pragma unroll
        for (int o = 16; o > 0; o >>= 1)
            acc += __shfl_down_sync(0xFFFFFFFFu, acc, o);
        if (lane == 0) {
            int be = b0 + e; if (be > B - 1) be = B - 1;
            out[be] = acc + fcb[0];
        }
    }
}

extern "C" void kernel_launch(void* const* d_in, const int* in_sizes, int n_in,
                              void* d_out, int out_size)
{
    const float* x    = (const float*)d_in[0];
    const float* Wih0 = (const float*)d_in[1];
    const float* Whh0 = (const float*)d_in[2];
    const float* bih0 = (const float*)d_in[3];
    const float* bhh0 = (const float*)d_in[4];
    const float* Wih1 = (const float*)d_in[5];
    const float* Whh1 = (const float*)d_in[6];
    const float* bih1 = (const float*)d_in[7];
    const float* bhh1 = (const float*)d_in[8];
    const float* fcW  = (const float*)d_in[9];
    const float* fcb  = (const float*)d_in[10];
    float* out = (float*)d_out;

    int B = in_sizes[0] / T_STEPS;
    if (B < 1) B = 1;
    int blocks = (B + EPB - 1) / EPB;

    static bool attr_set = false;
    if (!attr_set) {
        cudaFuncSetAttribute(lstm_fused, cudaFuncAttributeMaxDynamicSharedMemorySize,
                             SMEM_TOTAL);
        attr_set = true;
    }

    lstm_fused<<<blocks, NTHR, SMEM_TOTAL>>>(x, Wih0, Whh0, bih0, bhh0,
                                             Wih1, Whh1, bih1, bhh1,
                                             fcW, fcb, out, B);
}

// round 5
// speedup vs baseline: 1.1280x; 1.1280x over previous
#include <cuda_runtime.h>
#include <cstdint>

#define T_STEPS 2048
#define HID 64
#define EPB 7
#define NTHR 512

typedef unsigned long long u64;

// ---------- f32x2 packed math ----------
__device__ __forceinline__ u64 fma2(u64 a, u64 b, u64 c) {
    u64 d; asm("fma.rn.f32x2 %0, %1, %2, %3;" : "=l"(d) : "l"(a), "l"(b), "l"(c)); return d;
}
__device__ __forceinline__ u64 pack2(float lo, float hi) {
    u64 d; asm("mov.b64 %0, {%1, %2};" : "=l"(d) : "f"(lo), "f"(hi)); return d;
}
__device__ __forceinline__ float2 unpack2(u64 v) {
    float a, b; asm("mov.b64 {%0, %1}, %2;" : "=f"(a), "=f"(b) : "l"(v));
    return make_float2(a, b);
}

// ---------- exact-ish activations (EX2+RCP; proven 1.6e-6 end-to-end) ----------
__device__ __forceinline__ float sigmoid_(float x) {
    return __fdividef(1.0f, 1.0f + __expf(-x));
}
__device__ __forceinline__ float tanh_(float x) {
    float e = __expf(2.0f * fabsf(x));
    float t = 1.0f - __fdividef(2.0f, e + 1.0f);
    return copysignf(t, x);
}

extern __shared__ float smem_f[];

// SMEM layout (float offsets)
#define OX   0
#define OH1  (EPB * T_STEPS)                 // 14336
#define OH2  (OH1 + 2 * EPB * HID)           // +896
#define OP0  (OH2 + 2 * EPB * HID)           // psh0: [8][EPB][HID] float2
#define OP1  (OP0 + 2 * 8 * EPB * HID)
#define OB0  (OP1 + 2 * 8 * EPB * HID)
#define OB1  (OB0 + 4 * HID)
#define OXW  (OB1 + 4 * HID)
#define SMEM_FLOATS (OXW + 4 * HID)          // 31232 floats = 124928 B

__global__ void __launch_bounds__(NTHR, 1)
lstm_fused(const float* __restrict__ x,
           const float* __restrict__ Wih0, const float* __restrict__ Whh0,
           const float* __restrict__ bih0, const float* __restrict__ bhh0,
           const float* __restrict__ Wih1, const float* __restrict__ Whh1,
           const float* __restrict__ bih1, const float* __restrict__ bhh1,
           const float* __restrict__ fcW,  const float* __restrict__ fcb,
           float* __restrict__ out, int B)
{
    float*  xs   = smem_f + OX;
    float*  h1f  = smem_f + OH1;
    float*  h2f  = smem_f + OH2;
    float2* psh0 = (float2*)(smem_f + OP0);
    float2* psh1 = (float2*)(smem_f + OP1);
    float4* b0s  = (float4*)(smem_f + OB0);
    float4* b1s  = (float4*)(smem_f + OB1);
    float4* xws  = (float4*)(smem_f + OXW);

    const int tid = threadIdx.x;
    const int u   = tid & 63;
    const int gp  = (tid >> 6) & 1;
    const int s   = tid >> 7;
    const int q   = s * 2 + gp;          // 0..7
    const int b0e = blockIdx.x * EPB;

    // ---- stage x rows ----
    for (int i = tid; i < EPB * T_STEPS / 4; i += NTHR) {
        int e = i / (T_STEPS / 4), c = i % (T_STEPS / 4);
        int be = b0e + e; if (be > B - 1) be = B - 1;
        ((float4*)xs)[i] = ((const float4*)(x + (size_t)be * T_STEPS))[c];
    }
    if (tid < HID) {
        b0s[tid] = make_float4(bih0[tid]       + bhh0[tid],
                               bih0[64 + tid]  + bhh0[64 + tid],
                               bih0[128 + tid] + bhh0[128 + tid],
                               bih0[192 + tid] + bhh0[192 + tid]);
        b1s[tid] = make_float4(bih1[tid]       + bhh1[tid],
                               bih1[64 + tid]  + bhh1[64 + tid],
                               bih1[128 + tid] + bhh1[128 + tid],
                               bih1[192 + tid] + bhh1[192 + tid]);
        xws[tid] = make_float4(Wih0[tid], Wih0[64 + tid],
                               Wih0[128 + tid], Wih0[192 + tid]);
    }
    for (int i = tid; i < 2 * EPB * HID; i += NTHR) { h1f[i] = 0.0f; h2f[i] = 0.0f; }

    // ---- register weights (k-pair packed f32x2) ----
    const int rA = (gp * 2) * 64 + u, rB = (gp * 2 + 1) * 64 + u;
    u64 w0A[8], w0B[8];
    {
        const int k0 = s * 16;
#pragma unroll
        for (int p = 0; p < 8; ++p) {
            w0A[p] = pack2(Whh0[rA * 64 + k0 + 2 * p], Whh0[rA * 64 + k0 + 2 * p + 1]);
            w0B[p] = pack2(Whh0[rB * 64 + k0 + 2 * p], Whh0[rB * 64 + k0 + 2 * p + 1]);
        }
    }
    u64 w1A[16], w1B[16];
    {
        const float* Wsrc = (s < 2) ? Wih1 : Whh1;
        const int kb = (s & 1) * 32;
#pragma unroll
        for (int p = 0; p < 16; ++p) {
            w1A[p] = pack2(Wsrc[rA * 64 + kb + 2 * p], Wsrc[rA * 64 + kb + 2 * p + 1]);
            w1B[p] = pack2(Wsrc[rB * 64 + kb + 2 * p], Wsrc[rB * 64 + kb + 2 * p + 1]);
        }
    }

    // ---- precomputed phase-1 writer bases ----
    float2* pw0 = psh0 + (q * EPB) * HID + u;
    float2* pw1 = psh1 + (q * EPB) * HID + u;

    // ---- precomputed phase-2 task state ----
    // task0: q<7 -> (L0, e=q); q==7 -> (L1, e=0).  task1: q<6 -> (L1, e=q+1).
    const bool t0L1 = (q == 7);
    const int  e0   = t0L1 ? 0 : q;
    const float2* pr0 = (t0L1 ? psh1 : psh0) + e0 * HID + u;
    float*        hs0 = (t0L1 ? h2f : h1f) + e0 * HID + u;
    const float*  xb0 = xs + e0 * T_STEPS;
    const float4* bp0 = (t0L1 ? b1s : b0s) + u;
    const bool has1 = (q < 6);
    const int  e1   = has1 ? (q + 1) : 0;
    const float2* pr1 = psh1 + e1 * HID + u;
    float*        hs1 = h2f + e1 * HID + u;
    const float4* bp1 = b1s + u;
    const float4* xwp = xws + u;

    float cA = 0.0f, cB = 0.0f;
    __syncthreads();

#define Q (EPB * HID)   // 448: psh stride per q-slot (float2 units)

#pragma unroll 1
    for (int j = 0; j <= T_STEPS; ++j) {
        const int rb = j & 1;

        // ================= phase 1 =================
        if (j < T_STEPS) {     // layer0 partials for step j (reads h1[j-1])
            const ulonglong2* hp = (const ulonglong2*)(h1f + rb * Q) + s * 4;
#pragma unroll
            for (int e = 0; e < EPB; ++e) {
                ulonglong2 v0 = hp[e * 16 + 0], v1 = hp[e * 16 + 1];
                ulonglong2 v2 = hp[e * 16 + 2], v3 = hp[e * 16 + 3];
                u64 aA = 0, aB = 0;
                aA = fma2(v0.x, w0A[0], aA); aB = fma2(v0.x, w0B[0], aB);
                aA = fma2(v0.y, w0A[1], aA); aB = fma2(v0.y, w0B[1], aB);
                aA = fma2(v1.x, w0A[2], aA); aB = fma2(v1.x, w0B[2], aB);
                aA = fma2(v1.y, w0A[3], aA); aB = fma2(v1.y, w0B[3], aB);
                aA = fma2(v2.x, w0A[4], aA); aB = fma2(v2.x, w0B[4], aB);
                aA = fma2(v2.y, w0A[5], aA); aB = fma2(v2.y, w0B[5], aB);
                aA = fma2(v3.x, w0A[6], aA); aB = fma2(v3.x, w0B[6], aB);
                aA = fma2(v3.y, w0A[7], aA); aB = fma2(v3.y, w0B[7], aB);
                float2 fa = unpack2(aA), fb = unpack2(aB);
                pw0[e * HID] = make_float2(fa.x + fa.y, fb.x + fb.y);
            }
        }
        if (j > 0) {           // layer1 partials for step j-1 (reads h1[j-1], h2[j-2])
            const ulonglong2* hp = (s < 2)
                ? (const ulonglong2*)(h1f + rb * Q) + s * 8
                : (const ulonglong2*)(h2f + rb * Q) + (s - 2) * 8;
#pragma unroll
            for (int e = 0; e < EPB; ++e) {
                u64 aA = 0, aB = 0;
#pragma unroll
                for (int p = 0; p < 8; ++p) {
                    ulonglong2 v = hp[e * 16 + p];
                    aA = fma2(v.x, w1A[2 * p], aA);     aB = fma2(v.x, w1B[2 * p], aB);
                    aA = fma2(v.y, w1A[2 * p + 1], aA); aB = fma2(v.y, w1B[2 * p + 1], aB);
                }
                float2 fa = unpack2(aA), fb = unpack2(aB);
                pw1[e * HID] = make_float2(fa.x + fa.y, fb.x + fb.y);
            }
        }
        __syncthreads();

        // ================= phase 2 =================
        const int wo = (rb ^ 1) * Q;
        const bool act0 = t0L1 ? (j > 0) : (j < T_STEPS);
        if (act0) {
            float2 a0 = pr0[0 * Q], a1 = pr0[2 * Q], a2 = pr0[4 * Q], a3 = pr0[6 * Q];
            float2 g0 = pr0[1 * Q], g1 = pr0[3 * Q], g2 = pr0[5 * Q], g3 = pr0[7 * Q];
            float4 bb = *bp0;
            float pi = a0.x + a1.x + a2.x + a3.x + bb.x;
            float pf = a0.y + a1.y + a2.y + a3.y + bb.y;
            float pg = g0.x + g1.x + g2.x + g3.x + bb.z;
            float po = g0.y + g1.y + g2.y + g3.y + bb.w;
            if (!t0L1) {
                float xv = xb0[j];
                float4 xw = *xwp;
                pi += xv * xw.x; pf += xv * xw.y; pg += xv * xw.z; po += xv * xw.w;
            }
            float gi = sigmoid_(pi), gf = sigmoid_(pf);
            float gg = tanh_(pg),    go = sigmoid_(po);
            cA = gf * cA + gi * gg;
            hs0[wo] = go * tanh_(cA);
        }
        if (has1 && j > 0) {
            float2 a0 = pr1[0 * Q], a1 = pr1[2 * Q], a2 = pr1[4 * Q], a3 = pr1[6 * Q];
            float2 g0 = pr1[1 * Q], g1 = pr1[3 * Q], g2 = pr1[5 * Q], g3 = pr1[7 * Q];
            float4 bb = *bp1;
            float pi = a0.x + a1.x + a2.x + a3.x + bb.x;
            float pf = a0.y + a1.y + a2.y + a3.y + bb.y;
            float pg = g0.x + g1.x + g2.x + g3.x + bb.z;
            float po = g0.y + g1.y + g2.y + g3.y + bb.w;
            float gi = sigmoid_(pi), gf = sigmoid_(pf);
            float gg = tanh_(pg),    go = sigmoid_(po);
            cB = gf * cB + gi * gg;
            hs1[wo] = go * tanh_(cB);
        }
        __syncthreads();
    }

    // ---- final FC: h2[T-1] lives in slot 1 ----
    if (tid < EPB * 32) {
        const int e = tid >> 5, lane = tid & 31;
        const float* h2l = h2f + (1 * EPB + e) * HID;
        float acc = h2l[lane] * fcW[lane] + h2l[32 + lane] * fcW[32 + lane];
#pragma unroll
        for (int o = 16; o > 0; o >>= 1)
            acc += __shfl_down_sync(0xFFFFFFFFu, acc, o);
        if (lane == 0) {
            int be = b0e + e; if (be > B - 1) be = B - 1;
            out[be] = acc + fcb[0];
        }
    }
#undef Q
}

extern "C" void kernel_launch(void* const* d_in, const int* in_sizes, int n_in,
                              void* d_out, int out_size)
{
    const float* x    = (const float*)d_in[0];
    const float* Wih0 = (const float*)d_in[1];
    const float* Whh0 = (const float*)d_in[2];
    const float* bih0 = (const float*)d_in[3];
    const float* bhh0 = (const float*)d_in[4];
    const float* Wih1 = (const float*)d_in[5];
    const float* Whh1 = (const float*)d_in[6];
    const float* bih1 = (const float*)d_in[7];
    const float* bhh1 = (const float*)d_in[8];
    const float* fcW  = (const float*)d_in[9];
    const float* fcb  = (const float*)d_in[10];
    float* out = (float*)d_out;

    int B = in_sizes[0] / T_STEPS;
    if (B < 1) B = 1;
    int blocks = (B + EPB - 1) / EPB;

    const int smem_bytes = SMEM_FLOATS * 4;
    cudaFuncSetAttribute(lstm_fused, cudaFuncAttributeMaxDynamicSharedMemorySize,
                         smem_bytes);

    lstm_fused<<<blocks, NTHR, smem_bytes>>>(x, Wih0, Whh0, bih0, bhh0,
                                             Wih1, Whh1, bih1, bhh1,
                                             fcW, fcb, out, B);
}